// round 16
// baseline (speedup 1.0000x reference)
#include <cuda_runtime.h>
#include <cuda_fp16.h>
#include <stdint.h>
#include <math.h>

#define NN   50000
#define EE   640000
#define ETOT (EE + NN)
#define DD   128

typedef __half fp16;

// ---------------- scratch (device globals; no allocation allowed) ----------
__device__ __align__(16) fp16  g_CATh[(size_t)NN * 256];
__device__ __align__(16) fp16  g_Xh [(size_t)NN * DD];
__device__ __align__(16) fp16  g_Xl [(size_t)NN * DD];
__device__ __align__(16) fp16  g_AGGh[(size_t)NN * DD];
__device__ __align__(16) fp16  g_H1h[(size_t)NN * DD];
__device__ __align__(16) fp16  g_H1l[(size_t)NN * DD];
__device__ __align__(16) fp16  g_P1h[(size_t)NN * DD];
__device__ __align__(16) fp16  g_P2h[(size_t)NN * DD];
__device__ __align__(16) fp16  g_XPh[(size_t)NN * DD];
__device__ __align__(16) fp16  g_SKIPh[(size_t)NN * DD];
__device__ __align__(16) fp16  g_GI [(size_t)NN * 3 * DD];
__device__ __align__(16) fp16  g_GH1[(size_t)NN * 3 * DD];
__device__ __align__(16) fp16  g_GH2[(size_t)NN * 3 * DD];
#define WT_TOTAL 278528
__device__ __align__(16) fp16  g_WTh[WT_TOTAL];
__device__ float g_ASRC[NN];
__device__ float g_ADST[NN];
__device__ float g_BN[256];
__device__ int   g_deg[NN];
__device__ int   g_off[NN + 1];
__device__ int   g_cur[NN];
__device__ int   g_csr[ETOT];

// WT segment offsets (elems): merge, gat1, wih1, whh1, gat2, wih2, whh2, skip
#define WOFF_MERGE 0
#define WOFF_GAT1  32768
#define WOFF_WIH1  49152
#define WOFF_WHH1  98304
#define WOFF_GAT2  147456
#define WOFF_WIH2  163840
#define WOFF_WHH2  212992
#define WOFF_SKIP  262144

// ---------------- helpers ----------------------------------------------------
__device__ __forceinline__ uint32_t smem_u32(const void* p) {
    uint32_t a;
    asm("{ .reg .u64 t; cvta.to.shared.u64 t, %1; cvt.u32.u64 %0, t; }"
        : "=r"(a) : "l"(p));
    return a;
}
__device__ __forceinline__ void split2h(float x0, float x1,
                                        uint32_t& hi, uint32_t& lo) {
    __half2 h = __floats2half2_rn(x0, x1);
    float r0 = x0 - __half2float(__low2half(h));
    float r1 = x1 - __half2float(__high2half(h));
    __half2 l = __floats2half2_rn(r0, r1);
    hi = *reinterpret_cast<uint32_t*>(&h);
    lo = *reinterpret_cast<uint32_t*>(&l);
}
__device__ __forceinline__ void mma_f16(float c[4], const uint32_t a[4],
                                        uint32_t b0, uint32_t b1) {
    asm volatile(
        "mma.sync.aligned.m16n8k16.row.col.f32.f16.f16.f32 "
        "{%0,%1,%2,%3}, {%4,%5,%6,%7}, {%8,%9}, {%0,%1,%2,%3};"
        : "+f"(c[0]), "+f"(c[1]), "+f"(c[2]), "+f"(c[3])
        : "r"(a[0]), "r"(a[1]), "r"(a[2]), "r"(a[3]), "r"(b0), "r"(b1));
}
#define LDSM4(R, addr) \
    asm volatile("ldmatrix.sync.aligned.m8n8.x4.shared.b16 {%0,%1,%2,%3}, [%4];" \
        : "=r"((R)[0]), "=r"((R)[1]), "=r"((R)[2]), "=r"((R)[3]) : "r"(addr))
#define CP16(dst, src, sz) \
    asm volatile("cp.async.cg.shared.global [%0], [%1], 16, %2;" \
        :: "r"(dst), "l"(src), "r"(sz))
#define CP_COMMIT() asm volatile("cp.async.commit_group;")
#define CP_WAIT0()  asm volatile("cp.async.wait_group 0;" ::: "memory")

// ---------------- batched fp16 split GEMM ------------------------------------
// D = Ah*Wh (+ Al*Wh when Al != nullptr)
struct GemmJob {
    const fp16 *Ah, *Al, *Wh;
    const float* bias;
    float* C;
    fp16* C16;
    fp16 *Chi; fp16 *Clo;
    int nrows, K, M, gx;
    const float *as_, *ad_;
    float *os_, *od_;
};
struct GemmBatch { GemmJob j[3]; };

#define FSTRIDE  272
#define FARR     34816
#define SM_TOT   104448
#define SAB     144
#define OFF_AH  0
#define OFF_AL  18432
#define OFF_BH  36864

__global__ __launch_bounds__(256, 2) void gemm_mma(GemmBatch batch)
{
    const GemmJob job = batch.j[blockIdx.z];
    if ((int)blockIdx.x >= job.gx) return;
    const bool hasAl = (job.Al != nullptr);

    extern __shared__ char dsm[];
    const uint32_t sb = smem_u32(dsm);

    const int tid = threadIdx.x;
    const int wid = tid >> 5, lane = tid & 31;
    const int g = lane >> 2, tg = lane & 3;
    const int wr = (wid & 3) * 32;
    const int wc = (wid >> 2) * 64;
    const int row0 = blockIdx.y * 128;
    const int col0 = blockIdx.x * 128;
    const int K = job.K, M = job.M, nrows = job.nrows;

    float c[2][8][4];
#pragma unroll
    for (int mt = 0; mt < 2; mt++)
#pragma unroll
        for (int nt = 0; nt < 8; nt++)
#pragma unroll
            for (int j = 0; j < 4; j++) c[mt][nt][j] = 0.f;

    const uint32_t lrow = lane & 15;
    const uint32_t lkb  = (lane >> 4) * 16;

    if (K == 128) {
#pragma unroll
        for (int i = 0; i < 24; i++) {
            const int slot = i * 256 + tid;
            const int arr = slot >> 11;
            const int rem = slot & 2047;
            const int r = rem >> 4, gk = rem & 15;
            const uint32_t dst = sb + arr * FARR + r * FSTRIDE + gk * 16;
            if (arr == 2) {
                CP16(dst, job.Wh + (size_t)(col0 + r) * 128 + gk * 8, 16);
            } else if (arr == 0 || hasAl) {
                const fp16* src = (arr ? job.Al : job.Ah)
                    + (size_t)(row0 + r) * 128 + gk * 8;
                const int ok = (row0 + r < nrows) ? 16 : 0;
                CP16(dst, src, ok);
            }
        }
        CP_COMMIT();
        CP_WAIT0();
        __syncthreads();

#pragma unroll
        for (int ks = 0; ks < 8; ks++) {
            const uint32_t kb = (uint32_t)(ks * 32) + lkb;
            uint32_t ah[2][4], al[2][4], bh[4][4];
#pragma unroll
            for (int mt = 0; mt < 2; mt++) {
                const uint32_t aoff = (uint32_t)((wr + mt * 16 + lrow) * FSTRIDE) + kb;
                LDSM4(ah[mt], sb + aoff);
                if (hasAl) LDSM4(al[mt], sb + FARR + aoff);
            }
#pragma unroll
            for (int ntp = 0; ntp < 4; ntp++) {
                const uint32_t boff = (uint32_t)((wc + ntp * 16 + lrow) * FSTRIDE) + kb;
                LDSM4(bh[ntp], sb + 2 * FARR + boff);
            }
#pragma unroll
            for (int ntp = 0; ntp < 4; ntp++)
#pragma unroll
                for (int mt = 0; mt < 2; mt++)
#pragma unroll
                    for (int nb = 0; nb < 2; nb++) {
                        float* cc = c[mt][ntp * 2 + nb];
                        mma_f16(cc, ah[mt], bh[ntp][nb], bh[ntp][2 + nb]);
                        if (hasAl)
                            mma_f16(cc, al[mt], bh[ntp][nb], bh[ntp][2 + nb]);
                    }
        }
    } else {
        const uint32_t sAh = sb + OFF_AH, sAl = sb + OFF_AL, sBh = sb + OFF_BH;
        const int nchunks = K >> 6;
        for (int ch = 0; ch < nchunks; ch++) {
            const int k0 = ch << 6;
            if (ch > 0) __syncthreads();
#pragma unroll
            for (int i = 0; i < 12; i++) {
                const int slot = i * 256 + tid;
                const int arr = slot >> 10;
                const int rem = slot & 1023;
                const int r = rem >> 3, gk = rem & 7;
                const uint32_t dst = (arr == 0 ? sAh : (arr == 1 ? sAl : sBh))
                    + (uint32_t)(r * SAB + gk * 16);
                if (arr == 2) {
                    CP16(dst, job.Wh + (size_t)(col0 + r) * K + k0 + gk * 8, 16);
                } else if (arr == 0 || hasAl) {
                    const fp16* src = (arr ? job.Al : job.Ah)
                        + (size_t)(row0 + r) * K + k0 + gk * 8;
                    const int ok = (row0 + r < nrows) ? 16 : 0;
                    CP16(dst, src, ok);
                }
            }
            CP_COMMIT();
            CP_WAIT0();
            __syncthreads();
#pragma unroll
            for (int ks = 0; ks < 4; ks++) {
                const uint32_t kb = (uint32_t)(ks * 32) + lkb;
                uint32_t ah[2][4], al[2][4], bh[4][4];
#pragma unroll
                for (int mt = 0; mt < 2; mt++) {
                    const uint32_t aoff = (uint32_t)((wr + mt * 16 + lrow) * SAB) + kb;
                    LDSM4(ah[mt], sAh + aoff);
                    if (hasAl) LDSM4(al[mt], sAl + aoff);
                }
#pragma unroll
                for (int ntp = 0; ntp < 4; ntp++) {
                    const uint32_t boff = (uint32_t)((wc + ntp * 16 + lrow) * SAB) + kb;
                    LDSM4(bh[ntp], sBh + boff);
                }
#pragma unroll
                for (int ntp = 0; ntp < 4; ntp++)
#pragma unroll
                    for (int mt = 0; mt < 2; mt++)
#pragma unroll
                        for (int nb = 0; nb < 2; nb++) {
                            float* cc = c[mt][ntp * 2 + nb];
                            mma_f16(cc, ah[mt], bh[ntp][nb], bh[ntp][2 + nb]);
                            if (hasAl)
                                mma_f16(cc, al[mt], bh[ntp][nb], bh[ntp][2 + nb]);
                        }
            }
        }
    }

    // ---- epilogue ----
    float ss[2][2] = {{0.f, 0.f}, {0.f, 0.f}};
    float sd[2][2] = {{0.f, 0.f}, {0.f, 0.f}};
#pragma unroll
    for (int mt = 0; mt < 2; mt++) {
#pragma unroll
        for (int nt = 0; nt < 8; nt++) {
            const int colL = wc + nt * 8 + tg * 2;
            const int col = col0 + colL;
            float b0 = 0.f, b1 = 0.f;
            if (job.bias) { b0 = job.bias[col]; b1 = job.bias[col + 1]; }
            const float v0 = c[mt][nt][0] + b0;
            const float v1 = c[mt][nt][1] + b1;
            const float v2 = c[mt][nt][2] + b0;
            const float v3 = c[mt][nt][3] + b1;
            const int rA = row0 + wr + mt * 16 + g;
            const int rB = rA + 8;
            if (job.C) {
                if (rA < nrows) *(float2*)&job.C[(size_t)rA * M + col] = make_float2(v0, v1);
                if (rB < nrows) *(float2*)&job.C[(size_t)rB * M + col] = make_float2(v2, v3);
            }
            if (job.C16) {
                if (rA < nrows) {
                    __half2 p = __floats2half2_rn(v0, v1);
                    *(__half2*)&job.C16[(size_t)rA * M + col] = p;
                }
                if (rB < nrows) {
                    __half2 p = __floats2half2_rn(v2, v3);
                    *(__half2*)&job.C16[(size_t)rB * M + col] = p;
                }
            }
            if (job.Chi) {
                uint32_t h, l;
                if (rA < nrows) {
                    split2h(v0, v1, h, l);
                    *(uint32_t*)&job.Chi[(size_t)rA * M + col] = h;
                    *(uint32_t*)&job.Clo[(size_t)rA * M + col] = l;
                }
                if (rB < nrows) {
                    split2h(v2, v3, h, l);
                    *(uint32_t*)&job.Chi[(size_t)rB * M + col] = h;
                    *(uint32_t*)&job.Clo[(size_t)rB * M + col] = l;
                }
            }
            if (job.os_) {
                const float s0 = job.as_[colL], s1 = job.as_[colL + 1];
                const float d0 = job.ad_[colL], d1 = job.ad_[colL + 1];
                ss[mt][0] += v0 * s0 + v1 * s1;
                ss[mt][1] += v2 * s0 + v3 * s1;
                sd[mt][0] += v0 * d0 + v1 * d1;
                sd[mt][1] += v2 * d0 + v3 * d1;
            }
        }
    }
    if (job.os_) {
        float* red_s = (float*)dsm;
        float* red_d = red_s + 256;
        __syncthreads();
#pragma unroll
        for (int mt = 0; mt < 2; mt++)
#pragma unroll
            for (int h = 0; h < 2; h++) {
                ss[mt][h] += __shfl_xor_sync(0xffffffffu, ss[mt][h], 1);
                ss[mt][h] += __shfl_xor_sync(0xffffffffu, ss[mt][h], 2);
                sd[mt][h] += __shfl_xor_sync(0xffffffffu, sd[mt][h], 1);
                sd[mt][h] += __shfl_xor_sync(0xffffffffu, sd[mt][h], 2);
            }
        if (tg == 0) {
            const int wcid = wid >> 2;
#pragma unroll
            for (int mt = 0; mt < 2; mt++)
#pragma unroll
                for (int h = 0; h < 2; h++) {
                    const int rl = wr + mt * 16 + h * 8 + g;
                    red_s[wcid * 128 + rl] = ss[mt][h];
                    red_d[wcid * 128 + rl] = sd[mt][h];
                }
        }
        __syncthreads();
        if (tid < 128) {
            const int r = row0 + tid;
            if (r < nrows) {
                job.os_[r] = red_s[tid] + red_s[128 + tid];
                job.od_[r] = red_d[tid] + red_d[128 + tid];
            }
        }
    }
}

// ---------------- one-shot weight truncate + transpose ----------------------
__global__ void k_wsplit(const float* w0, const float* w1, const float* w2,
                         const float* w3, const float* w4, const float* w5,
                         const float* w6, const float* w7)
{
    int idx = blockIdx.x * blockDim.x + threadIdx.x;
    if (idx >= WT_TOTAL) return;
    const int offs[9] = {WOFF_MERGE, WOFF_GAT1, WOFF_WIH1, WOFF_WHH1,
                         WOFF_GAT2, WOFF_WIH2, WOFF_WHH2, WOFF_SKIP, WT_TOTAL};
    const int Ks[8] = {256, 128, 128, 128, 128, 128, 128, 128};
    const int Ms[8] = {128, 128, 384, 384, 128, 384, 384, 128};
    const float* ws[8] = {w0, w1, w2, w3, w4, w5, w6, w7};
    int s = 0;
#pragma unroll
    for (int i = 1; i < 8; i++) if (idx >= offs[i]) s = i;
    const int local = idx - offs[s];
    const int K = Ks[s], M = Ms[s];
    const int m = local / K, k = local % K;
    g_WTh[idx] = __float2half_rn(ws[s][(size_t)k * M + m]);
}

// ---------------- fused prep (+ edge degree count) ---------------------------
__global__ void k_prep(const float* __restrict__ nf, const float* __restrict__ ts,
                       const float* __restrict__ freq, const float* __restrict__ phase,
                       const float* __restrict__ xp1, const float* __restrict__ xp2,
                       const int* __restrict__ ei)
{
    int idx = blockIdx.x * blockDim.x + threadIdx.x;
    if (idx >= NN * DD) return;
    if (idx < ETOT) {
        int d = (idx < EE) ? ei[EE + idx] : (idx - EE);
        atomicAdd(&g_deg[d], 1);
    }
    int n = idx >> 7, j = idx & 127;
    float a = nf[idx];
    float b = cosf(ts[n] * freq[j] + phase[j]);
    size_t base = (size_t)n * 256;
    g_CATh[base + j] = __float2half_rn(a);
    g_CATh[base + 128 + j] = __float2half_rn(b);
    g_P1h[idx] = __float2half_rn(xp1[idx]);
    g_P2h[idx] = __float2half_rn(xp2[idx]);
}

// ---------------- graph / CSR build -----------------------------------------
__global__ void k_scan() {
    __shared__ int wsum[32];
    __shared__ int carry;
    const int tid = threadIdx.x, lane = tid & 31, w = tid >> 5;
    if (tid == 0) carry = 0;
    __syncthreads();
    for (int base = 0; base < NN; base += 1024) {
        const int v = base + tid;
        const int x = (v < NN) ? g_deg[v] : 0;
        int s = x;
#pragma unroll
        for (int o = 1; o < 32; o <<= 1) {
            int t = __shfl_up_sync(0xffffffffu, s, o);
            if (lane >= o) s += t;
        }
        if (lane == 31) wsum[w] = s;
        __syncthreads();
        if (w == 0) {
            int ws = wsum[lane];
#pragma unroll
            for (int o = 1; o < 32; o <<= 1) {
                int t = __shfl_up_sync(0xffffffffu, ws, o);
                if (lane >= o) ws += t;
            }
            wsum[lane] = ws;
        }
        __syncthreads();
        const int pre = (w > 0) ? wsum[w - 1] : 0;
        const int excl = carry + pre + s - x;
        const int tot = wsum[31];
        if (v < NN) { g_off[v] = excl; g_cur[v] = excl; }
        __syncthreads();
        if (tid == 0) carry += tot;
        __syncthreads();
    }
    if (tid == 0) g_off[NN] = carry;
}
__global__ void k_csr_scatter(const int* __restrict__ ei) {
    int i = blockIdx.x * blockDim.x + threadIdx.x;
    if (i < ETOT) {
        int s, d;
        if (i < EE) { s = ei[i]; d = ei[EE + i]; }
        else        { s = i - EE; d = i - EE; }
        int slot = atomicAdd(&g_cur[d], 1);
        g_csr[slot] = s;
    }
}

// ---------------- GAT aggregation: fp16 gather, fp32 accumulate -------------
__global__ void k_gat_agg(const fp16* __restrict__ XP,
                          const float* __restrict__ bias,
                          fp16* __restrict__ oh)
{
    int v = (blockIdx.x * blockDim.x + threadIdx.x) >> 5;
    int lane = threadIdx.x & 31;
    if (v >= NN) return;
    const int beg = g_off[v], end = g_off[v + 1];
    const float adv = g_ADST[v];

    float ssum = 0.f;
    float4 acc = make_float4(0.f, 0.f, 0.f, 0.f);
    int i = beg;
    for (; i + 3 < end; i += 4) {
        const int s0 = g_csr[i],     s1 = g_csr[i + 1];
        const int s2 = g_csr[i + 2], s3 = g_csr[i + 3];
        float e0 = g_ASRC[s0] + adv, e1 = g_ASRC[s1] + adv;
        float e2 = g_ASRC[s2] + adv, e3 = g_ASRC[s3] + adv;
        e0 = (e0 > 0.f) ? e0 : 0.2f * e0;
        e1 = (e1 > 0.f) ? e1 : 0.2f * e1;
        e2 = (e2 > 0.f) ? e2 : 0.2f * e2;
        e3 = (e3 > 0.f) ? e3 : 0.2f * e3;
        const float w0 = expf(e0), w1 = expf(e1);
        const float w2 = expf(e2), w3 = expf(e3);
        ssum += (w0 + w1) + (w2 + w3);
        const uint2 r0 = *(const uint2*)&XP[(size_t)s0 * DD + lane * 4];
        const uint2 r1 = *(const uint2*)&XP[(size_t)s1 * DD + lane * 4];
        const uint2 r2 = *(const uint2*)&XP[(size_t)s2 * DD + lane * 4];
        const uint2 r3 = *(const uint2*)&XP[(size_t)s3 * DD + lane * 4];
        float2 a0 = __half22float2(*(const __half2*)&r0.x);
        float2 b0 = __half22float2(*(const __half2*)&r0.y);
        float2 a1 = __half22float2(*(const __half2*)&r1.x);
        float2 b1 = __half22float2(*(const __half2*)&r1.y);
        float2 a2 = __half22float2(*(const __half2*)&r2.x);
        float2 b2 = __half22float2(*(const __half2*)&r2.y);
        float2 a3 = __half22float2(*(const __half2*)&r3.x);
        float2 b3 = __half22float2(*(const __half2*)&r3.y);
        acc.x += w0 * a0.x + w1 * a1.x + w2 * a2.x + w3 * a3.x;
        acc.y += w0 * a0.y + w1 * a1.y + w2 * a2.y + w3 * a3.y;
        acc.z += w0 * b0.x + w1 * b1.x + w2 * b2.x + w3 * b3.x;
        acc.w += w0 * b0.y + w1 * b1.y + w2 * b2.y + w3 * b3.y;
    }
    for (; i < end; i++) {
        const int s0 = g_csr[i];
        float e0 = g_ASRC[s0] + adv;
        e0 = (e0 > 0.f) ? e0 : 0.2f * e0;
        const float w0 = expf(e0);
        ssum += w0;
        const uint2 r0 = *(const uint2*)&XP[(size_t)s0 * DD + lane * 4];
        float2 a0 = __half22float2(*(const __half2*)&r0.x);
        float2 b0 = __half22float2(*(const __half2*)&r0.y);
        acc.x += w0 * a0.x; acc.y += w0 * a0.y;
        acc.z += w0 * b0.x; acc.w += w0 * b0.y;
    }
    const float inv = 1.f / (ssum + 1e-16f);
    const float4 b4 = *(const float4*)&bias[lane * 4];
    __half2 h01 = __floats2half2_rn(acc.x * inv + b4.x, acc.y * inv + b4.y);
    __half2 h23 = __floats2half2_rn(acc.z * inv + b4.z, acc.w * inv + b4.w);
    const size_t base = (size_t)v * DD + lane * 4;
    *(__half2*)&oh[base]     = h01;
    *(__half2*)&oh[base + 2] = h23;
}

// ---------------- GRU gates (grid-stride, optional fused BN reduction) ------
__global__ void k_gru(const fp16* __restrict__ GI, const fp16* __restrict__ GH,
                      const float* __restrict__ h, const fp16* __restrict__ skip,
                      float* __restrict__ out, fp16* __restrict__ oh,
                      fp16* __restrict__ ol, int do_relu, int do_bn)
{
    const int total = NN * DD / 2;
    const int tid = threadIdx.x;
    float ls0 = 0.f, ls1 = 0.f, lq0 = 0.f, lq1 = 0.f;
    for (int idx = blockIdx.x * blockDim.x + tid; idx < total;
         idx += gridDim.x * blockDim.x) {
        const int n = idx >> 6;
        const int j = (idx & 63) * 2;
        const size_t base = (size_t)n * 3 * DD;
        const float2 ir = __half22float2(*(const __half2*)&GI[base + j]);
        const float2 iz = __half22float2(*(const __half2*)&GI[base + DD + j]);
        const float2 in_ = __half22float2(*(const __half2*)&GI[base + 2 * DD + j]);
        const float2 hr = __half22float2(*(const __half2*)&GH[base + j]);
        const float2 hz = __half22float2(*(const __half2*)&GH[base + DD + j]);
        const float2 hn = __half22float2(*(const __half2*)&GH[base + 2 * DD + j]);
        const size_t oidx = (size_t)n * DD + j;
        const float2 hv = *(const float2*)&h[oidx];
        float r0 = 1.f / (1.f + expf(-(ir.x + hr.x)));
        float r1 = 1.f / (1.f + expf(-(ir.y + hr.y)));
        float z0 = 1.f / (1.f + expf(-(iz.x + hz.x)));
        float z1 = 1.f / (1.f + expf(-(iz.y + hz.y)));
        float n0 = tanhf(in_.x + r0 * hn.x);
        float n1 = tanhf(in_.y + r1 * hn.y);
        float o0 = (1.f - z0) * n0 + z0 * hv.x;
        float o1 = (1.f - z1) * n1 + z1 * hv.y;
        if (skip) {
            const float2 sk = __half22float2(*(const __half2*)&skip[oidx]);
            o0 += sk.x; o1 += sk.y;
        }
        if (do_relu) { o0 = fmaxf(o0, 0.f); o1 = fmaxf(o1, 0.f); }
        *(float2*)&out[oidx] = make_float2(o0, o1);
        if (oh) {
            uint32_t hh, ll;
            split2h(o0, o1, hh, ll);
            *(uint32_t*)&oh[oidx] = hh;
            *(uint32_t*)&ol[oidx] = ll;
        }
        if (do_bn) {
            ls0 += o0; lq0 += o0 * o0;
            ls1 += o1; lq1 += o1 * o1;
        }
    }
    if (do_bn) {
        // stride is a multiple of 64 -> each thread has a fixed column pair:
        // p = tid & 63, columns 2p and 2p+1.
        __shared__ float sm[4][256];
        sm[0][tid] = ls0; sm[1][tid] = ls1;
        sm[2][tid] = lq0; sm[3][tid] = lq1;
        __syncthreads();
        if (tid < 64) {
            float a0 = 0.f, a1 = 0.f, q0 = 0.f, q1 = 0.f;
#pragma unroll
            for (int k = 0; k < 4; k++) {
                a0 += sm[0][tid + 64 * k];
                a1 += sm[1][tid + 64 * k];
                q0 += sm[2][tid + 64 * k];
                q1 += sm[3][tid + 64 * k];
            }
            const int c = tid * 2;
            atomicAdd(&g_BN[c],       a0);
            atomicAdd(&g_BN[c + 1],   a1);
            atomicAdd(&g_BN[128 + c],     q0);
            atomicAdd(&g_BN[128 + c + 1], q1);
        }
    }
}

// ---------------- BatchNorm normalize ----------------------------------------
__global__ void k_bn_norm(float* __restrict__ H2) {
    int idx = blockIdx.x * blockDim.x + threadIdx.x;
    if (idx >= NN * DD) return;
    int j = idx & 127;
    float mu = g_BN[j] * (1.f / NN);
    float var = g_BN[128 + j] * (1.f / NN) - mu * mu;
    H2[idx] = (H2[idx] - mu) * rsqrtf(var + 1e-5f);
}

// ---------------- launch ------------------------------------------------------
extern "C" void kernel_launch(void* const* d_in, const int* in_sizes, int n_in,
                              void* d_out, int out_size)
{
    const float* nf       = (const float*)d_in[0];
    const int*   ei       = (const int*)  d_in[1];
    const float* x_prev1  = (const float*)d_in[2];
    const float* x_prev2  = (const float*)d_in[3];
    const float* ts       = (const float*)d_in[4];
    const float* freq     = (const float*)d_in[5];
    const float* phase    = (const float*)d_in[6];
    const float* merge_W  = (const float*)d_in[7];
    const float* merge_b  = (const float*)d_in[8];
    const float* gat1_W   = (const float*)d_in[9];
    const float* gat1_as  = (const float*)d_in[10];
    const float* gat1_ad  = (const float*)d_in[11];
    const float* gat1_b   = (const float*)d_in[12];
    const float* gru1_Wih = (const float*)d_in[13];
    const float* gru1_Whh = (const float*)d_in[14];
    const float* gru1_bih = (const float*)d_in[15];
    const float* gru1_bhh = (const float*)d_in[16];
    const float* gat2_W   = (const float*)d_in[17];
    const float* gat2_as  = (const float*)d_in[18];
    const float* gat2_ad  = (const float*)d_in[19];
    const float* gat2_b   = (const float*)d_in[20];
    const float* gru2_Wih = (const float*)d_in[21];
    const float* gru2_Whh = (const float*)d_in[22];
    const float* gru2_bih = (const float*)d_in[23];
    const float* gru2_bhh = (const float*)d_in[24];
    const float* skip_W   = (const float*)d_in[25];
    const float* skip_b   = (const float*)d_in[26];

    float* H1 = (float*)d_out;
    float* H2 = H1 + (size_t)NN * DD;

    float *pBN, *pAS, *pAD;
    fp16 *pXPh, *pSKIPh, *pGI, *pGH1, *pGH2;
    fp16 *pCATh, *pXh, *pXl, *pAGGh, *pH1h, *pH1l;
    fp16 *pP1h, *pP2h, *pWTh;
    int *pDeg;
    cudaGetSymbolAddress((void**)&pXPh,   g_XPh);
    cudaGetSymbolAddress((void**)&pSKIPh, g_SKIPh);
    cudaGetSymbolAddress((void**)&pGI,    g_GI);
    cudaGetSymbolAddress((void**)&pGH1,   g_GH1);
    cudaGetSymbolAddress((void**)&pGH2,   g_GH2);
    cudaGetSymbolAddress((void**)&pBN,    g_BN);
    cudaGetSymbolAddress((void**)&pAS,    g_ASRC);
    cudaGetSymbolAddress((void**)&pAD,    g_ADST);
    cudaGetSymbolAddress((void**)&pCATh,  g_CATh);
    cudaGetSymbolAddress((void**)&pXh,    g_Xh);
    cudaGetSymbolAddress((void**)&pXl,    g_Xl);
    cudaGetSymbolAddress((void**)&pAGGh,  g_AGGh);
    cudaGetSymbolAddress((void**)&pH1h,   g_H1h);
    cudaGetSymbolAddress((void**)&pH1l,   g_H1l);
    cudaGetSymbolAddress((void**)&pP1h,   g_P1h);
    cudaGetSymbolAddress((void**)&pP2h,   g_P2h);
    cudaGetSymbolAddress((void**)&pWTh,   g_WTh);
    cudaGetSymbolAddress((void**)&pDeg,   g_deg);

    cudaFuncSetAttribute(gemm_mma, cudaFuncAttributeMaxDynamicSharedMemorySize,
                         SM_TOT);

    const int TB = 256;
    const int gb_edges = (ETOT + TB - 1) / TB;
    const int gb_nd    = (NN * DD + TB - 1) / TB;
    const int gb_nd2   = (NN * DD / 2 + TB - 1) / TB;
    const int gb_warp  = (NN * 32 + TB - 1) / TB;
    const int rtiles   = (NN + 127) / 128;
    const int gru2_blocks = 782;    // stride 782*256 divisible by 64

    GemmJob jz = {};

    cudaMemsetAsync(pDeg, 0, NN * sizeof(int));
    cudaMemsetAsync(pBN, 0, 256 * sizeof(float));

    k_prep<<<gb_nd, TB>>>(nf, ts, freq, phase, x_prev1, x_prev2, ei);
    k_wsplit<<<(WT_TOTAL + TB - 1) / TB, TB>>>(merge_W, gat1_W, gru1_Wih,
        gru1_Whh, gat2_W, gru2_Wih, gru2_Whh, skip_W);

    // BATCH1: merge GEMM (no-split in, split out) + GH1 + GH2 (no-split)
    {
        GemmBatch b; b.j[0] = jz; b.j[1] = jz; b.j[2] = jz;
        b.j[0].Ah = pCATh;
        b.j[0].Wh = pWTh + WOFF_MERGE;
        b.j[0].bias = merge_b; b.j[0].Chi = pXh; b.j[0].Clo = pXl;
        b.j[0].nrows = NN; b.j[0].K = 256; b.j[0].M = DD; b.j[0].gx = 1;
        b.j[1].Ah = pP1h;
        b.j[1].Wh = pWTh + WOFF_WHH1;
        b.j[1].bias = gru1_bhh; b.j[1].C16 = pGH1;
        b.j[1].nrows = NN; b.j[1].K = 128; b.j[1].M = 384; b.j[1].gx = 3;
        b.j[2].Ah = pP2h;
        b.j[2].Wh = pWTh + WOFF_WHH2;
        b.j[2].bias = gru2_bhh; b.j[2].C16 = pGH2;
        b.j[2].nrows = NN; b.j[2].K = 128; b.j[2].M = 384; b.j[2].gx = 3;
        gemm_mma<<<dim3(3, rtiles, 3), 256, SM_TOT>>>(b);
    }
    k_scan<<<1, 1024>>>();
    k_csr_scatter<<<gb_edges, TB>>>(ei);

    // layer 1: GAT projection (+attn dots, split) batched with skip GEMM
    {
        GemmBatch b; b.j[0] = jz; b.j[1] = jz; b.j[2] = jz;
        b.j[0].Ah = pXh; b.j[0].Al = pXl;
        b.j[0].Wh = pWTh + WOFF_GAT1;
        b.j[0].C16 = pXPh; b.j[0].nrows = NN; b.j[0].K = 128; b.j[0].M = DD;
        b.j[0].gx = 1; b.j[0].as_ = gat1_as; b.j[0].ad_ = gat1_ad;
        b.j[0].os_ = pAS; b.j[0].od_ = pAD;
        b.j[1].Ah = pXh;
        b.j[1].Wh = pWTh + WOFF_SKIP;
        b.j[1].bias = skip_b; b.j[1].C16 = pSKIPh;
        b.j[1].nrows = NN; b.j[1].K = 128; b.j[1].M = DD; b.j[1].gx = 1;
        gemm_mma<<<dim3(1, rtiles, 2), 256, SM_TOT>>>(b);
    }
    k_gat_agg<<<gb_warp, TB>>>(pXPh, gat1_b, pAGGh);
    {
        GemmBatch b; b.j[0] = jz; b.j[1] = jz; b.j[2] = jz;
        b.j[0].Ah = pAGGh;
        b.j[0].Wh = pWTh + WOFF_WIH1;
        b.j[0].bias = gru1_bih; b.j[0].C16 = pGI;
        b.j[0].nrows = NN; b.j[0].K = 128; b.j[0].M = 384; b.j[0].gx = 3;
        gemm_mma<<<dim3(3, rtiles, 1), 256, SM_TOT>>>(b);
    }
    k_gru<<<gb_nd2, TB>>>(pGI, pGH1, x_prev1, nullptr, H1, pH1h, pH1l, 1, 0);

    // layer 2: gat2 projection (+attn, split)
    {
        GemmBatch b; b.j[0] = jz; b.j[1] = jz; b.j[2] = jz;
        b.j[0].Ah = pH1h; b.j[0].Al = pH1l;
        b.j[0].Wh = pWTh + WOFF_GAT2;
        b.j[0].C16 = pXPh; b.j[0].nrows = NN; b.j[0].K = 128; b.j[0].M = DD;
        b.j[0].gx = 1; b.j[0].as_ = gat2_as; b.j[0].ad_ = gat2_ad;
        b.j[0].os_ = pAS; b.j[0].od_ = pAD;
        gemm_mma<<<dim3(1, rtiles, 1), 256, SM_TOT>>>(b);
    }
    k_gat_agg<<<gb_warp, TB>>>(pXPh, gat2_b, pAGGh);
    {
        GemmBatch b; b.j[0] = jz; b.j[1] = jz; b.j[2] = jz;
        b.j[0].Ah = pAGGh;
        b.j[0].Wh = pWTh + WOFF_WIH2;
        b.j[0].bias = gru2_bih; b.j[0].C16 = pGI;
        b.j[0].nrows = NN; b.j[0].K = 128; b.j[0].M = 384; b.j[0].gx = 3;
        gemm_mma<<<dim3(3, rtiles, 1), 256, SM_TOT>>>(b);
    }
    // layer 2 GRU with fused BN reduction (grid-stride; stride % 64 == 0)
    k_gru<<<gru2_blocks, TB>>>(pGI, pGH2, x_prev2, pSKIPh, H2,
                               nullptr, nullptr, 0, 1);

    // BatchNorm normalize
    k_bn_norm<<<gb_nd, TB>>>(H2);
}

// round 17
// speedup vs baseline: 1.0963x; 1.0963x over previous
#include <cuda_runtime.h>
#include <cuda_fp16.h>
#include <stdint.h>
#include <math.h>

#define NN   50000
#define EE   640000
#define ETOT (EE + NN)
#define DD   128
#define SCAN_B 196           // ceil(NN/256)

typedef __half fp16;

// ---------------- scratch (device globals; no allocation allowed) ----------
__device__ __align__(16) fp16  g_CATh[(size_t)NN * 256];
__device__ __align__(16) fp16  g_Xh [(size_t)NN * DD];
__device__ __align__(16) fp16  g_Xl [(size_t)NN * DD];
__device__ __align__(16) fp16  g_AGGh[(size_t)NN * DD];
__device__ __align__(16) fp16  g_H1h[(size_t)NN * DD];
__device__ __align__(16) fp16  g_H1l[(size_t)NN * DD];
__device__ __align__(16) fp16  g_P1h[(size_t)NN * DD];
__device__ __align__(16) fp16  g_P2h[(size_t)NN * DD];
__device__ __align__(16) fp16  g_XPh[(size_t)NN * DD];
__device__ __align__(16) fp16  g_SKIPh[(size_t)NN * DD];
__device__ __align__(16) fp16  g_GI [(size_t)NN * 3 * DD];
__device__ __align__(16) fp16  g_GH1[(size_t)NN * 3 * DD];
__device__ __align__(16) fp16  g_GH2[(size_t)NN * 3 * DD];
#define WT_TOTAL 278528
__device__ __align__(16) fp16  g_WTh[WT_TOTAL];
__device__ float g_ASRC[NN];
__device__ float g_ADST[NN];
__device__ float g_BN[256];
__device__ int   g_deg[NN];
__device__ int   g_off[NN + 1];
__device__ int   g_cur[NN];
__device__ int   g_bsum[SCAN_B];
__device__ int   g_csr[ETOT];

// WT segment offsets (elems): merge, gat1, wih1, whh1, gat2, wih2, whh2, skip
#define WOFF_MERGE 0
#define WOFF_GAT1  32768
#define WOFF_WIH1  49152
#define WOFF_WHH1  98304
#define WOFF_GAT2  147456
#define WOFF_WIH2  163840
#define WOFF_WHH2  212992
#define WOFF_SKIP  262144

// ---------------- helpers ----------------------------------------------------
__device__ __forceinline__ uint32_t smem_u32(const void* p) {
    uint32_t a;
    asm("{ .reg .u64 t; cvta.to.shared.u64 t, %1; cvt.u32.u64 %0, t; }"
        : "=r"(a) : "l"(p));
    return a;
}
__device__ __forceinline__ void split2h(float x0, float x1,
                                        uint32_t& hi, uint32_t& lo) {
    __half2 h = __floats2half2_rn(x0, x1);
    float r0 = x0 - __half2float(__low2half(h));
    float r1 = x1 - __half2float(__high2half(h));
    __half2 l = __floats2half2_rn(r0, r1);
    hi = *reinterpret_cast<uint32_t*>(&h);
    lo = *reinterpret_cast<uint32_t*>(&l);
}
__device__ __forceinline__ void mma_f16(float c[4], const uint32_t a[4],
                                        uint32_t b0, uint32_t b1) {
    asm volatile(
        "mma.sync.aligned.m16n8k16.row.col.f32.f16.f16.f32 "
        "{%0,%1,%2,%3}, {%4,%5,%6,%7}, {%8,%9}, {%0,%1,%2,%3};"
        : "+f"(c[0]), "+f"(c[1]), "+f"(c[2]), "+f"(c[3])
        : "r"(a[0]), "r"(a[1]), "r"(a[2]), "r"(a[3]), "r"(b0), "r"(b1));
}
#define LDSM4(R, addr) \
    asm volatile("ldmatrix.sync.aligned.m8n8.x4.shared.b16 {%0,%1,%2,%3}, [%4];" \
        : "=r"((R)[0]), "=r"((R)[1]), "=r"((R)[2]), "=r"((R)[3]) : "r"(addr))
#define CP16(dst, src, sz) \
    asm volatile("cp.async.cg.shared.global [%0], [%1], 16, %2;" \
        :: "r"(dst), "l"(src), "r"(sz))
#define CP_COMMIT() asm volatile("cp.async.commit_group;")
#define CP_WAIT0()  asm volatile("cp.async.wait_group 0;" ::: "memory")

// ---------------- batched fp16 split GEMM ------------------------------------
// D = Ah*Wh (+ Al*Wh when Al != nullptr)
struct GemmJob {
    const fp16 *Ah, *Al, *Wh;
    const float* bias;
    float* C;
    fp16* C16;
    fp16 *Chi; fp16 *Clo;
    int nrows, K, M, gx;
    const float *as_, *ad_;
    float *os_, *od_;
};
struct GemmBatch { GemmJob j[3]; };

#define FSTRIDE  272
#define FARR     34816
#define SM_TOT   104448
#define SAB     144
#define OFF_AH  0
#define OFF_AL  18432
#define OFF_BH  36864

__global__ __launch_bounds__(256, 2) void gemm_mma(GemmBatch batch)
{
    const GemmJob job = batch.j[blockIdx.z];
    if ((int)blockIdx.x >= job.gx) return;
    const bool hasAl = (job.Al != nullptr);

    extern __shared__ char dsm[];
    const uint32_t sb = smem_u32(dsm);

    const int tid = threadIdx.x;
    const int wid = tid >> 5, lane = tid & 31;
    const int g = lane >> 2, tg = lane & 3;
    const int wr = (wid & 3) * 32;
    const int wc = (wid >> 2) * 64;
    const int row0 = blockIdx.y * 128;
    const int col0 = blockIdx.x * 128;
    const int K = job.K, M = job.M, nrows = job.nrows;

    float c[2][8][4];
#pragma unroll
    for (int mt = 0; mt < 2; mt++)
#pragma unroll
        for (int nt = 0; nt < 8; nt++)
#pragma unroll
            for (int j = 0; j < 4; j++) c[mt][nt][j] = 0.f;

    const uint32_t lrow = lane & 15;
    const uint32_t lkb  = (lane >> 4) * 16;

    if (K == 128) {
#pragma unroll
        for (int i = 0; i < 24; i++) {
            const int slot = i * 256 + tid;
            const int arr = slot >> 11;
            const int rem = slot & 2047;
            const int r = rem >> 4, gk = rem & 15;
            const uint32_t dst = sb + arr * FARR + r * FSTRIDE + gk * 16;
            if (arr == 2) {
                CP16(dst, job.Wh + (size_t)(col0 + r) * 128 + gk * 8, 16);
            } else if (arr == 0 || hasAl) {
                const fp16* src = (arr ? job.Al : job.Ah)
                    + (size_t)(row0 + r) * 128 + gk * 8;
                const int ok = (row0 + r < nrows) ? 16 : 0;
                CP16(dst, src, ok);
            }
        }
        CP_COMMIT();
        CP_WAIT0();
        __syncthreads();

#pragma unroll
        for (int ks = 0; ks < 8; ks++) {
            const uint32_t kb = (uint32_t)(ks * 32) + lkb;
            uint32_t ah[2][4], al[2][4], bh[4][4];
#pragma unroll
            for (int mt = 0; mt < 2; mt++) {
                const uint32_t aoff = (uint32_t)((wr + mt * 16 + lrow) * FSTRIDE) + kb;
                LDSM4(ah[mt], sb + aoff);
                if (hasAl) LDSM4(al[mt], sb + FARR + aoff);
            }
#pragma unroll
            for (int ntp = 0; ntp < 4; ntp++) {
                const uint32_t boff = (uint32_t)((wc + ntp * 16 + lrow) * FSTRIDE) + kb;
                LDSM4(bh[ntp], sb + 2 * FARR + boff);
            }
#pragma unroll
            for (int ntp = 0; ntp < 4; ntp++)
#pragma unroll
                for (int mt = 0; mt < 2; mt++)
#pragma unroll
                    for (int nb = 0; nb < 2; nb++) {
                        float* cc = c[mt][ntp * 2 + nb];
                        mma_f16(cc, ah[mt], bh[ntp][nb], bh[ntp][2 + nb]);
                        if (hasAl)
                            mma_f16(cc, al[mt], bh[ntp][nb], bh[ntp][2 + nb]);
                    }
        }
    } else {
        const uint32_t sAh = sb + OFF_AH, sAl = sb + OFF_AL, sBh = sb + OFF_BH;
        const int nchunks = K >> 6;
        for (int ch = 0; ch < nchunks; ch++) {
            const int k0 = ch << 6;
            if (ch > 0) __syncthreads();
#pragma unroll
            for (int i = 0; i < 12; i++) {
                const int slot = i * 256 + tid;
                const int arr = slot >> 10;
                const int rem = slot & 1023;
                const int r = rem >> 3, gk = rem & 7;
                const uint32_t dst = (arr == 0 ? sAh : (arr == 1 ? sAl : sBh))
                    + (uint32_t)(r * SAB + gk * 16);
                if (arr == 2) {
                    CP16(dst, job.Wh + (size_t)(col0 + r) * K + k0 + gk * 8, 16);
                } else if (arr == 0 || hasAl) {
                    const fp16* src = (arr ? job.Al : job.Ah)
                        + (size_t)(row0 + r) * K + k0 + gk * 8;
                    const int ok = (row0 + r < nrows) ? 16 : 0;
                    CP16(dst, src, ok);
                }
            }
            CP_COMMIT();
            CP_WAIT0();
            __syncthreads();
#pragma unroll
            for (int ks = 0; ks < 4; ks++) {
                const uint32_t kb = (uint32_t)(ks * 32) + lkb;
                uint32_t ah[2][4], al[2][4], bh[4][4];
#pragma unroll
                for (int mt = 0; mt < 2; mt++) {
                    const uint32_t aoff = (uint32_t)((wr + mt * 16 + lrow) * SAB) + kb;
                    LDSM4(ah[mt], sAh + aoff);
                    if (hasAl) LDSM4(al[mt], sAl + aoff);
                }
#pragma unroll
                for (int ntp = 0; ntp < 4; ntp++) {
                    const uint32_t boff = (uint32_t)((wc + ntp * 16 + lrow) * SAB) + kb;
                    LDSM4(bh[ntp], sBh + boff);
                }
#pragma unroll
                for (int ntp = 0; ntp < 4; ntp++)
#pragma unroll
                    for (int mt = 0; mt < 2; mt++)
#pragma unroll
                        for (int nb = 0; nb < 2; nb++) {
                            float* cc = c[mt][ntp * 2 + nb];
                            mma_f16(cc, ah[mt], bh[ntp][nb], bh[ntp][2 + nb]);
                            if (hasAl)
                                mma_f16(cc, al[mt], bh[ntp][nb], bh[ntp][2 + nb]);
                        }
            }
        }
    }

    // ---- epilogue ----
    float ss[2][2] = {{0.f, 0.f}, {0.f, 0.f}};
    float sd[2][2] = {{0.f, 0.f}, {0.f, 0.f}};
#pragma unroll
    for (int mt = 0; mt < 2; mt++) {
#pragma unroll
        for (int nt = 0; nt < 8; nt++) {
            const int colL = wc + nt * 8 + tg * 2;
            const int col = col0 + colL;
            float b0 = 0.f, b1 = 0.f;
            if (job.bias) { b0 = job.bias[col]; b1 = job.bias[col + 1]; }
            const float v0 = c[mt][nt][0] + b0;
            const float v1 = c[mt][nt][1] + b1;
            const float v2 = c[mt][nt][2] + b0;
            const float v3 = c[mt][nt][3] + b1;
            const int rA = row0 + wr + mt * 16 + g;
            const int rB = rA + 8;
            if (job.C) {
                if (rA < nrows) *(float2*)&job.C[(size_t)rA * M + col] = make_float2(v0, v1);
                if (rB < nrows) *(float2*)&job.C[(size_t)rB * M + col] = make_float2(v2, v3);
            }
            if (job.C16) {
                if (rA < nrows) {
                    __half2 p = __floats2half2_rn(v0, v1);
                    *(__half2*)&job.C16[(size_t)rA * M + col] = p;
                }
                if (rB < nrows) {
                    __half2 p = __floats2half2_rn(v2, v3);
                    *(__half2*)&job.C16[(size_t)rB * M + col] = p;
                }
            }
            if (job.Chi) {
                uint32_t h, l;
                if (rA < nrows) {
                    split2h(v0, v1, h, l);
                    *(uint32_t*)&job.Chi[(size_t)rA * M + col] = h;
                    *(uint32_t*)&job.Clo[(size_t)rA * M + col] = l;
                }
                if (rB < nrows) {
                    split2h(v2, v3, h, l);
                    *(uint32_t*)&job.Chi[(size_t)rB * M + col] = h;
                    *(uint32_t*)&job.Clo[(size_t)rB * M + col] = l;
                }
            }
            if (job.os_) {
                const float s0 = job.as_[colL], s1 = job.as_[colL + 1];
                const float d0 = job.ad_[colL], d1 = job.ad_[colL + 1];
                ss[mt][0] += v0 * s0 + v1 * s1;
                ss[mt][1] += v2 * s0 + v3 * s1;
                sd[mt][0] += v0 * d0 + v1 * d1;
                sd[mt][1] += v2 * d0 + v3 * d1;
            }
        }
    }
    if (job.os_) {
        float* red_s = (float*)dsm;
        float* red_d = red_s + 256;
        __syncthreads();
#pragma unroll
        for (int mt = 0; mt < 2; mt++)
#pragma unroll
            for (int h = 0; h < 2; h++) {
                ss[mt][h] += __shfl_xor_sync(0xffffffffu, ss[mt][h], 1);
                ss[mt][h] += __shfl_xor_sync(0xffffffffu, ss[mt][h], 2);
                sd[mt][h] += __shfl_xor_sync(0xffffffffu, sd[mt][h], 1);
                sd[mt][h] += __shfl_xor_sync(0xffffffffu, sd[mt][h], 2);
            }
        if (tg == 0) {
            const int wcid = wid >> 2;
#pragma unroll
            for (int mt = 0; mt < 2; mt++)
#pragma unroll
                for (int h = 0; h < 2; h++) {
                    const int rl = wr + mt * 16 + h * 8 + g;
                    red_s[wcid * 128 + rl] = ss[mt][h];
                    red_d[wcid * 128 + rl] = sd[mt][h];
                }
        }
        __syncthreads();
        if (tid < 128) {
            const int r = row0 + tid;
            if (r < nrows) {
                job.os_[r] = red_s[tid] + red_s[128 + tid];
                job.od_[r] = red_d[tid] + red_d[128 + tid];
            }
        }
    }
}

// ---------------- one-shot weight truncate + transpose ----------------------
__global__ void k_wsplit(const float* w0, const float* w1, const float* w2,
                         const float* w3, const float* w4, const float* w5,
                         const float* w6, const float* w7)
{
    int idx = blockIdx.x * blockDim.x + threadIdx.x;
    if (idx >= WT_TOTAL) return;
    const int offs[9] = {WOFF_MERGE, WOFF_GAT1, WOFF_WIH1, WOFF_WHH1,
                         WOFF_GAT2, WOFF_WIH2, WOFF_WHH2, WOFF_SKIP, WT_TOTAL};
    const int Ks[8] = {256, 128, 128, 128, 128, 128, 128, 128};
    const int Ms[8] = {128, 128, 384, 384, 128, 384, 384, 128};
    const float* ws[8] = {w0, w1, w2, w3, w4, w5, w6, w7};
    int s = 0;
#pragma unroll
    for (int i = 1; i < 8; i++) if (idx >= offs[i]) s = i;
    const int local = idx - offs[s];
    const int K = Ks[s], M = Ms[s];
    const int m = local / K, k = local % K;
    g_WTh[idx] = __float2half_rn(ws[s][(size_t)k * M + m]);
}

// ---------------- fused prep (+ edge degree count) ---------------------------
__global__ void k_prep(const float* __restrict__ nf, const float* __restrict__ ts,
                       const float* __restrict__ freq, const float* __restrict__ phase,
                       const float* __restrict__ xp1, const float* __restrict__ xp2,
                       const int* __restrict__ ei)
{
    int idx = blockIdx.x * blockDim.x + threadIdx.x;
    if (idx >= NN * DD) return;
    if (idx < ETOT) {
        int d = (idx < EE) ? ei[EE + idx] : (idx - EE);
        atomicAdd(&g_deg[d], 1);
    }
    int n = idx >> 7, j = idx & 127;
    float a = nf[idx];
    float b = cosf(ts[n] * freq[j] + phase[j]);
    size_t base = (size_t)n * 256;
    g_CATh[base + j] = __float2half_rn(a);
    g_CATh[base + 128 + j] = __float2half_rn(b);
    g_P1h[idx] = __float2half_rn(xp1[idx]);
    g_P2h[idx] = __float2half_rn(xp2[idx]);
}

// ---------------- 3-phase parallel exclusive scan of g_deg -------------------
// phase 1: block-local exclusive scan -> g_off (local), block total -> g_bsum
__global__ void k_scan1() {
    __shared__ int wsum[8];
    const int tid = threadIdx.x, lane = tid & 31, w = tid >> 5;
    const int v = blockIdx.x * 256 + tid;
    const int x = (v < NN) ? g_deg[v] : 0;
    int s = x;
#pragma unroll
    for (int o = 1; o < 32; o <<= 1) {
        int t = __shfl_up_sync(0xffffffffu, s, o);
        if (lane >= o) s += t;
    }
    if (lane == 31) wsum[w] = s;
    __syncthreads();
    if (tid < 8) {
        int ws = wsum[tid];
#pragma unroll
        for (int o = 1; o < 8; o <<= 1) {
            int t = __shfl_up_sync(0xffu, ws, o);
            if (tid >= o) ws += t;
        }
        wsum[tid] = ws;
    }
    __syncthreads();
    const int pre = (w > 0) ? wsum[w - 1] : 0;
    if (v < NN) g_off[v] = pre + s - x;          // local exclusive
    if (tid == 255) g_bsum[blockIdx.x] = pre + s; // block total
}
// phase 2: 1 block scans SCAN_B block sums -> exclusive offsets; total -> g_off[NN]
__global__ void k_scan2() {
    __shared__ int wsum[8];
    const int tid = threadIdx.x, lane = tid & 31, w = tid >> 5;
    const int x = (tid < SCAN_B) ? g_bsum[tid] : 0;
    int s = x;
#pragma unroll
    for (int o = 1; o < 32; o <<= 1) {
        int t = __shfl_up_sync(0xffffffffu, s, o);
        if (lane >= o) s += t;
    }
    if (lane == 31) wsum[w] = s;
    __syncthreads();
    if (tid < 8) {
        int ws = wsum[tid];
#pragma unroll
        for (int o = 1; o < 8; o <<= 1) {
            int t = __shfl_up_sync(0xffu, ws, o);
            if (tid >= o) ws += t;
        }
        wsum[tid] = ws;
    }
    __syncthreads();
    const int pre = (w > 0) ? wsum[w - 1] : 0;
    if (tid < SCAN_B) g_bsum[tid] = pre + s - x;  // exclusive block offset
    if (tid == 255) g_off[NN] = wsum[7];          // grand total
}
// phase 3: add block offsets, write final g_off / g_cur
__global__ void k_scan3() {
    const int v = blockIdx.x * 256 + threadIdx.x;
    if (v < NN) {
        const int e = g_off[v] + g_bsum[blockIdx.x];
        g_off[v] = e;
        g_cur[v] = e;
    }
}

__global__ void k_csr_scatter(const int* __restrict__ ei) {
    int i = blockIdx.x * blockDim.x + threadIdx.x;
    if (i < ETOT) {
        int s, d;
        if (i < EE) { s = ei[i]; d = ei[EE + i]; }
        else        { s = i - EE; d = i - EE; }
        int slot = atomicAdd(&g_cur[d], 1);
        g_csr[slot] = s;
    }
}

// ---------------- GAT aggregation: fp16 gather, fp32 accumulate -------------
__global__ void k_gat_agg(const fp16* __restrict__ XP,
                          const float* __restrict__ bias,
                          fp16* __restrict__ oh)
{
    int v = (blockIdx.x * blockDim.x + threadIdx.x) >> 5;
    int lane = threadIdx.x & 31;
    if (v >= NN) return;
    const int beg = g_off[v], end = g_off[v + 1];
    const float adv = g_ADST[v];

    float ssum = 0.f;
    float4 acc = make_float4(0.f, 0.f, 0.f, 0.f);
    int i = beg;
    for (; i + 3 < end; i += 4) {
        const int s0 = g_csr[i],     s1 = g_csr[i + 1];
        const int s2 = g_csr[i + 2], s3 = g_csr[i + 3];
        float e0 = g_ASRC[s0] + adv, e1 = g_ASRC[s1] + adv;
        float e2 = g_ASRC[s2] + adv, e3 = g_ASRC[s3] + adv;
        e0 = (e0 > 0.f) ? e0 : 0.2f * e0;
        e1 = (e1 > 0.f) ? e1 : 0.2f * e1;
        e2 = (e2 > 0.f) ? e2 : 0.2f * e2;
        e3 = (e3 > 0.f) ? e3 : 0.2f * e3;
        const float w0 = expf(e0), w1 = expf(e1);
        const float w2 = expf(e2), w3 = expf(e3);
        ssum += (w0 + w1) + (w2 + w3);
        const uint2 r0 = *(const uint2*)&XP[(size_t)s0 * DD + lane * 4];
        const uint2 r1 = *(const uint2*)&XP[(size_t)s1 * DD + lane * 4];
        const uint2 r2 = *(const uint2*)&XP[(size_t)s2 * DD + lane * 4];
        const uint2 r3 = *(const uint2*)&XP[(size_t)s3 * DD + lane * 4];
        float2 a0 = __half22float2(*(const __half2*)&r0.x);
        float2 b0 = __half22float2(*(const __half2*)&r0.y);
        float2 a1 = __half22float2(*(const __half2*)&r1.x);
        float2 b1 = __half22float2(*(const __half2*)&r1.y);
        float2 a2 = __half22float2(*(const __half2*)&r2.x);
        float2 b2 = __half22float2(*(const __half2*)&r2.y);
        float2 a3 = __half22float2(*(const __half2*)&r3.x);
        float2 b3 = __half22float2(*(const __half2*)&r3.y);
        acc.x += w0 * a0.x + w1 * a1.x + w2 * a2.x + w3 * a3.x;
        acc.y += w0 * a0.y + w1 * a1.y + w2 * a2.y + w3 * a3.y;
        acc.z += w0 * b0.x + w1 * b1.x + w2 * b2.x + w3 * b3.x;
        acc.w += w0 * b0.y + w1 * b1.y + w2 * b2.y + w3 * b3.y;
    }
    for (; i < end; i++) {
        const int s0 = g_csr[i];
        float e0 = g_ASRC[s0] + adv;
        e0 = (e0 > 0.f) ? e0 : 0.2f * e0;
        const float w0 = expf(e0);
        ssum += w0;
        const uint2 r0 = *(const uint2*)&XP[(size_t)s0 * DD + lane * 4];
        float2 a0 = __half22float2(*(const __half2*)&r0.x);
        float2 b0 = __half22float2(*(const __half2*)&r0.y);
        acc.x += w0 * a0.x; acc.y += w0 * a0.y;
        acc.z += w0 * b0.x; acc.w += w0 * b0.y;
    }
    const float inv = 1.f / (ssum + 1e-16f);
    const float4 b4 = *(const float4*)&bias[lane * 4];
    __half2 h01 = __floats2half2_rn(acc.x * inv + b4.x, acc.y * inv + b4.y);
    __half2 h23 = __floats2half2_rn(acc.z * inv + b4.z, acc.w * inv + b4.w);
    const size_t base = (size_t)v * DD + lane * 4;
    *(__half2*)&oh[base]     = h01;
    *(__half2*)&oh[base + 2] = h23;
}

// ---------------- GRU gates (grid-stride, optional fused BN reduction) ------
__global__ void k_gru(const fp16* __restrict__ GI, const fp16* __restrict__ GH,
                      const float* __restrict__ h, const fp16* __restrict__ skip,
                      float* __restrict__ out, fp16* __restrict__ oh,
                      fp16* __restrict__ ol, int do_relu, int do_bn)
{
    const int total = NN * DD / 2;
    const int tid = threadIdx.x;
    float ls0 = 0.f, ls1 = 0.f, lq0 = 0.f, lq1 = 0.f;
    for (int idx = blockIdx.x * blockDim.x + tid; idx < total;
         idx += gridDim.x * blockDim.x) {
        const int n = idx >> 6;
        const int j = (idx & 63) * 2;
        const size_t base = (size_t)n * 3 * DD;
        const float2 ir = __half22float2(*(const __half2*)&GI[base + j]);
        const float2 iz = __half22float2(*(const __half2*)&GI[base + DD + j]);
        const float2 in_ = __half22float2(*(const __half2*)&GI[base + 2 * DD + j]);
        const float2 hr = __half22float2(*(const __half2*)&GH[base + j]);
        const float2 hz = __half22float2(*(const __half2*)&GH[base + DD + j]);
        const float2 hn = __half22float2(*(const __half2*)&GH[base + 2 * DD + j]);
        const size_t oidx = (size_t)n * DD + j;
        const float2 hv = *(const float2*)&h[oidx];
        float r0 = 1.f / (1.f + expf(-(ir.x + hr.x)));
        float r1 = 1.f / (1.f + expf(-(ir.y + hr.y)));
        float z0 = 1.f / (1.f + expf(-(iz.x + hz.x)));
        float z1 = 1.f / (1.f + expf(-(iz.y + hz.y)));
        float n0 = tanhf(in_.x + r0 * hn.x);
        float n1 = tanhf(in_.y + r1 * hn.y);
        float o0 = (1.f - z0) * n0 + z0 * hv.x;
        float o1 = (1.f - z1) * n1 + z1 * hv.y;
        if (skip) {
            const float2 sk = __half22float2(*(const __half2*)&skip[oidx]);
            o0 += sk.x; o1 += sk.y;
        }
        if (do_relu) { o0 = fmaxf(o0, 0.f); o1 = fmaxf(o1, 0.f); }
        *(float2*)&out[oidx] = make_float2(o0, o1);
        if (oh) {
            uint32_t hh, ll;
            split2h(o0, o1, hh, ll);
            *(uint32_t*)&oh[oidx] = hh;
            *(uint32_t*)&ol[oidx] = ll;
        }
        if (do_bn) {
            ls0 += o0; lq0 += o0 * o0;
            ls1 += o1; lq1 += o1 * o1;
        }
    }
    if (do_bn) {
        __shared__ float sm[4][256];
        sm[0][tid] = ls0; sm[1][tid] = ls1;
        sm[2][tid] = lq0; sm[3][tid] = lq1;
        __syncthreads();
        if (tid < 64) {
            float a0 = 0.f, a1 = 0.f, q0 = 0.f, q1 = 0.f;
#pragma unroll
            for (int k = 0; k < 4; k++) {
                a0 += sm[0][tid + 64 * k];
                a1 += sm[1][tid + 64 * k];
                q0 += sm[2][tid + 64 * k];
                q1 += sm[3][tid + 64 * k];
            }
            const int c = tid * 2;
            atomicAdd(&g_BN[c],       a0);
            atomicAdd(&g_BN[c + 1],   a1);
            atomicAdd(&g_BN[128 + c],     q0);
            atomicAdd(&g_BN[128 + c + 1], q1);
        }
    }
}

// ---------------- BatchNorm normalize ----------------------------------------
__global__ void k_bn_norm(float* __restrict__ H2) {
    int idx = blockIdx.x * blockDim.x + threadIdx.x;
    if (idx >= NN * DD) return;
    int j = idx & 127;
    float mu = g_BN[j] * (1.f / NN);
    float var = g_BN[128 + j] * (1.f / NN) - mu * mu;
    H2[idx] = (H2[idx] - mu) * rsqrtf(var + 1e-5f);
}

// ---------------- launch ------------------------------------------------------
extern "C" void kernel_launch(void* const* d_in, const int* in_sizes, int n_in,
                              void* d_out, int out_size)
{
    const float* nf       = (const float*)d_in[0];
    const int*   ei       = (const int*)  d_in[1];
    const float* x_prev1  = (const float*)d_in[2];
    const float* x_prev2  = (const float*)d_in[3];
    const float* ts       = (const float*)d_in[4];
    const float* freq     = (const float*)d_in[5];
    const float* phase    = (const float*)d_in[6];
    const float* merge_W  = (const float*)d_in[7];
    const float* merge_b  = (const float*)d_in[8];
    const float* gat1_W   = (const float*)d_in[9];
    const float* gat1_as  = (const float*)d_in[10];
    const float* gat1_ad  = (const float*)d_in[11];
    const float* gat1_b   = (const float*)d_in[12];
    const float* gru1_Wih = (const float*)d_in[13];
    const float* gru1_Whh = (const float*)d_in[14];
    const float* gru1_bih = (const float*)d_in[15];
    const float* gru1_bhh = (const float*)d_in[16];
    const float* gat2_W   = (const float*)d_in[17];
    const float* gat2_as  = (const float*)d_in[18];
    const float* gat2_ad  = (const float*)d_in[19];
    const float* gat2_b   = (const float*)d_in[20];
    const float* gru2_Wih = (const float*)d_in[21];
    const float* gru2_Whh = (const float*)d_in[22];
    const float* gru2_bih = (const float*)d_in[23];
    const float* gru2_bhh = (const float*)d_in[24];
    const float* skip_W   = (const float*)d_in[25];
    const float* skip_b   = (const float*)d_in[26];

    float* H1 = (float*)d_out;
    float* H2 = H1 + (size_t)NN * DD;

    float *pBN, *pAS, *pAD;
    fp16 *pXPh, *pSKIPh, *pGI, *pGH1, *pGH2;
    fp16 *pCATh, *pXh, *pXl, *pAGGh, *pH1h, *pH1l;
    fp16 *pP1h, *pP2h, *pWTh;
    int *pDeg;
    cudaGetSymbolAddress((void**)&pXPh,   g_XPh);
    cudaGetSymbolAddress((void**)&pSKIPh, g_SKIPh);
    cudaGetSymbolAddress((void**)&pGI,    g_GI);
    cudaGetSymbolAddress((void**)&pGH1,   g_GH1);
    cudaGetSymbolAddress((void**)&pGH2,   g_GH2);
    cudaGetSymbolAddress((void**)&pBN,    g_BN);
    cudaGetSymbolAddress((void**)&pAS,    g_ASRC);
    cudaGetSymbolAddress((void**)&pAD,    g_ADST);
    cudaGetSymbolAddress((void**)&pCATh,  g_CATh);
    cudaGetSymbolAddress((void**)&pXh,    g_Xh);
    cudaGetSymbolAddress((void**)&pXl,    g_Xl);
    cudaGetSymbolAddress((void**)&pAGGh,  g_AGGh);
    cudaGetSymbolAddress((void**)&pH1h,   g_H1h);
    cudaGetSymbolAddress((void**)&pH1l,   g_H1l);
    cudaGetSymbolAddress((void**)&pP1h,   g_P1h);
    cudaGetSymbolAddress((void**)&pP2h,   g_P2h);
    cudaGetSymbolAddress((void**)&pWTh,   g_WTh);
    cudaGetSymbolAddress((void**)&pDeg,   g_deg);

    cudaFuncSetAttribute(gemm_mma, cudaFuncAttributeMaxDynamicSharedMemorySize,
                         SM_TOT);

    const int TB = 256;
    const int gb_edges = (ETOT + TB - 1) / TB;
    const int gb_nd    = (NN * DD + TB - 1) / TB;
    const int gb_nd2   = (NN * DD / 2 + TB - 1) / TB;
    const int gb_warp  = (NN * 32 + TB - 1) / TB;
    const int rtiles   = (NN + 127) / 128;
    const int gru2_blocks = 782;

    GemmJob jz = {};

    cudaMemsetAsync(pDeg, 0, NN * sizeof(int));
    cudaMemsetAsync(pBN, 0, 256 * sizeof(float));

    k_prep<<<gb_nd, TB>>>(nf, ts, freq, phase, x_prev1, x_prev2, ei);
    k_wsplit<<<(WT_TOTAL + TB - 1) / TB, TB>>>(merge_W, gat1_W, gru1_Wih,
        gru1_Whh, gat2_W, gru2_Wih, gru2_Whh, skip_W);

    // BATCH1: merge GEMM (no-split in, split out) + GH1 + GH2 (no-split)
    {
        GemmBatch b; b.j[0] = jz; b.j[1] = jz; b.j[2] = jz;
        b.j[0].Ah = pCATh;
        b.j[0].Wh = pWTh + WOFF_MERGE;
        b.j[0].bias = merge_b; b.j[0].Chi = pXh; b.j[0].Clo = pXl;
        b.j[0].nrows = NN; b.j[0].K = 256; b.j[0].M = DD; b.j[0].gx = 1;
        b.j[1].Ah = pP1h;
        b.j[1].Wh = pWTh + WOFF_WHH1;
        b.j[1].bias = gru1_bhh; b.j[1].C16 = pGH1;
        b.j[1].nrows = NN; b.j[1].K = 128; b.j[1].M = 384; b.j[1].gx = 3;
        b.j[2].Ah = pP2h;
        b.j[2].Wh = pWTh + WOFF_WHH2;
        b.j[2].bias = gru2_bhh; b.j[2].C16 = pGH2;
        b.j[2].nrows = NN; b.j[2].K = 128; b.j[2].M = 384; b.j[2].gx = 3;
        gemm_mma<<<dim3(3, rtiles, 3), 256, SM_TOT>>>(b);
    }
    // parallel 3-phase scan (replaces 49us single-block scan)
    k_scan1<<<SCAN_B, 256>>>();
    k_scan2<<<1, 256>>>();
    k_scan3<<<SCAN_B, 256>>>();
    k_csr_scatter<<<gb_edges, TB>>>(ei);

    // layer 1: GAT projection (+attn dots, split) batched with skip GEMM
    {
        GemmBatch b; b.j[0] = jz; b.j[1] = jz; b.j[2] = jz;
        b.j[0].Ah = pXh; b.j[0].Al = pXl;
        b.j[0].Wh = pWTh + WOFF_GAT1;
        b.j[0].C16 = pXPh; b.j[0].nrows = NN; b.j[0].K = 128; b.j[0].M = DD;
        b.j[0].gx = 1; b.j[0].as_ = gat1_as; b.j[0].ad_ = gat1_ad;
        b.j[0].os_ = pAS; b.j[0].od_ = pAD;
        b.j[1].Ah = pXh;
        b.j[1].Wh = pWTh + WOFF_SKIP;
        b.j[1].bias = skip_b; b.j[1].C16 = pSKIPh;
        b.j[1].nrows = NN; b.j[1].K = 128; b.j[1].M = DD; b.j[1].gx = 1;
        gemm_mma<<<dim3(1, rtiles, 2), 256, SM_TOT>>>(b);
    }
    k_gat_agg<<<gb_warp, TB>>>(pXPh, gat1_b, pAGGh);
    {
        GemmBatch b; b.j[0] = jz; b.j[1] = jz; b.j[2] = jz;
        b.j[0].Ah = pAGGh;
        b.j[0].Wh = pWTh + WOFF_WIH1;
        b.j[0].bias = gru1_bih; b.j[0].C16 = pGI;
        b.j[0].nrows = NN; b.j[0].K = 128; b.j[0].M = 384; b.j[0].gx = 3;
        gemm_mma<<<dim3(3, rtiles, 1), 256, SM_TOT>>>(b);
    }
    k_gru<<<gb_nd2, TB>>>(pGI, pGH1, x_prev1, nullptr, H1, pH1h, pH1l, 1, 0);

    // layer 2: gat2 projection (+attn, split)
    {
        GemmBatch b; b.j[0] = jz; b.j[1] = jz; b.j[2] = jz;
        b.j[0].Ah = pH1h; b.j[0].Al = pH1l;
        b.j[0].Wh = pWTh + WOFF_GAT2;
        b.j[0].C16 = pXPh; b.j[0].nrows = NN; b.j[0].K = 128; b.j[0].M = DD;
        b.j[0].gx = 1; b.j[0].as_ = gat2_as; b.j[0].ad_ = gat2_ad;
        b.j[0].os_ = pAS; b.j[0].od_ = pAD;
        gemm_mma<<<dim3(1, rtiles, 1), 256, SM_TOT>>>(b);
    }
    k_gat_agg<<<gb_warp, TB>>>(pXPh, gat2_b, pAGGh);
    {
        GemmBatch b; b.j[0] = jz; b.j[1] = jz; b.j[2] = jz;
        b.j[0].Ah = pAGGh;
        b.j[0].Wh = pWTh + WOFF_WIH2;
        b.j[0].bias = gru2_bih; b.j[0].C16 = pGI;
        b.j[0].nrows = NN; b.j[0].K = 128; b.j[0].M = 384; b.j[0].gx = 3;
        gemm_mma<<<dim3(3, rtiles, 1), 256, SM_TOT>>>(b);
    }
    k_gru<<<gru2_blocks, TB>>>(pGI, pGH2, x_prev2, pSKIPh, H2,
                               nullptr, nullptr, 0, 1);

    // BatchNorm normalize
    k_bn_norm<<<gb_nd, TB>>>(H2);
}